// round 11
// baseline (speedup 1.0000x reference)
#include <cuda_runtime.h>
#include <cuda_fp16.h>
#include <math.h>
#include <stdint.h>

#define Bsz  2
#define Ssz  2048
#define HIDs 2048
#define NHh  16
#define HDd  128
#define Mrows (Bsz*Ssz)

__device__ __half g_hid[Mrows*HIDs];
__device__ __half g_q[Mrows*HIDs];
__device__ __half g_k[Mrows*HIDs];
__device__ __half g_v[Mrows*HIDs];
__device__ __half g_vt[Mrows*HIDs];     // [bh][d][s]
__device__ __half g_attn[Mrows*HIDs];
__device__ __half g_wq[HIDs*HIDs];      // [N][K]
__device__ __half g_wk[HIDs*HIDs];
__device__ __half g_wv[HIDs*HIDs];
__device__ __half g_wc[HIDs*HIDs];

__device__ __forceinline__ void mma16(float* c, const uint32_t* a, const uint32_t* b) {
    asm volatile(
        "mma.sync.aligned.m16n8k16.row.col.f32.f16.f16.f32 "
        "{%0,%1,%2,%3}, {%4,%5,%6,%7}, {%8,%9}, {%0,%1,%2,%3};"
        : "+f"(c[0]), "+f"(c[1]), "+f"(c[2]), "+f"(c[3])
        : "r"(a[0]), "r"(a[1]), "r"(a[2]), "r"(a[3]), "r"(b[0]), "r"(b[1]));
}
__device__ __forceinline__ void cp16(uint32_t saddr, const void* g) {
    asm volatile("cp.async.cg.shared.global [%0], [%1], 16;" :: "r"(saddr), "l"(g));
}
__device__ __forceinline__ uint32_t smem_u32(const void* p) {
    return (uint32_t)__cvta_generic_to_shared(p);
}
__device__ __forceinline__ void ldsm4(uint32_t* r, uint32_t addr) {
    asm volatile("ldmatrix.sync.aligned.m8n8.x4.shared.b16 {%0,%1,%2,%3}, [%4];"
        : "=r"(r[0]), "=r"(r[1]), "=r"(r[2]), "=r"(r[3]) : "r"(addr));
}
__device__ __forceinline__ uint32_t ex2h2(float x0, float x1) {
    __half2 h = __floats2half2_rn(x0, x1);
    uint32_t u = *reinterpret_cast<uint32_t*>(&h);
    uint32_t r;
    asm volatile("ex2.approx.f16x2 %0, %1;" : "=r"(r) : "r"(u));
    return r;
}

// ---------------- prep ----------------
__global__ void cvth(const float* __restrict__ in, __half* __restrict__ out, int n4) {
    int i = blockIdx.x * blockDim.x + threadIdx.x;
    if (i < n4) {
        float4 v = ((const float4*)in)[i];
        __half2 h0 = __floats2half2_rn(v.x, v.y);
        __half2 h1 = __floats2half2_rn(v.z, v.w);
        uint2 u;
        u.x = *reinterpret_cast<uint32_t*>(&h0);
        u.y = *reinterpret_cast<uint32_t*>(&h1);
        ((uint2*)out)[i] = u;
    }
}

__global__ void wtrh4(const float* __restrict__ i0, const float* __restrict__ i1,
                      const float* __restrict__ i2, const float* __restrict__ i3,
                      __half* __restrict__ o0, __half* __restrict__ o1,
                      __half* __restrict__ o2, __half* __restrict__ o3) {
    const float* in  = (blockIdx.z == 0) ? i0 : (blockIdx.z == 1) ? i1
                     : (blockIdx.z == 2) ? i2 : i3;
    __half* out      = (blockIdx.z == 0) ? o0 : (blockIdx.z == 1) ? o1
                     : (blockIdx.z == 2) ? o2 : o3;
    __shared__ float t[32][33];
    int bx = blockIdx.x << 5, by = blockIdx.y << 5;
#pragma unroll
    for (int i = 0; i < 4; i++) {
        int k = by + threadIdx.y + (i << 3);
        t[threadIdx.y + (i << 3)][threadIdx.x] = in[(size_t)k * HIDs + bx + threadIdx.x];
    }
    __syncthreads();
#pragma unroll
    for (int i = 0; i < 4; i++) {
        int n = bx + threadIdx.y + (i << 3);
        out[(size_t)n * HIDs + by + threadIdx.x] =
            __float2half(t[threadIdx.x][threadIdx.y + (i << 3)]);
    }
}

// v[b][s][h*128+d] -> vt[bh][d][s]
__global__ void vtrans(const __half* __restrict__ v, __half* __restrict__ vt) {
    __shared__ __half t[32][33];
    int bh = blockIdx.z;
    int b = bh >> 4, h = bh & 15;
    int s0 = blockIdx.x << 5, d0 = blockIdx.y << 5;
#pragma unroll
    for (int i = 0; i < 4; i++) {
        int s = s0 + threadIdx.y + (i << 3);
        t[threadIdx.y + (i << 3)][threadIdx.x] =
            v[((size_t)(b * Ssz + s)) * HIDs + h * HDd + d0 + threadIdx.x];
    }
    __syncthreads();
#pragma unroll
    for (int i = 0; i < 4; i++) {
        int d = d0 + threadIdx.y + (i << 3);
        vt[((size_t)bh * HDd + d) * Ssz + s0 + threadIdx.x] =
            t[threadIdx.x][threadIdx.y + (i << 3)];
    }
}

// --------- fp16 GEMM 128x128 body, ldmatrix feeds, 2 CTA/SM, 4 stages -------
#define GST 40
#define G_STAGE_H (2*128*GST)           // 10240 halfs / stage
#define G_SMEM (4*G_STAGE_H*2)          // 81920 B

__device__ __forceinline__
void gemm_body(const __half* __restrict__ A, const __half* __restrict__ Bt,
               const float* __restrict__ bias, void* __restrict__ Cout,
               int out_half, __half* gsm, int bmq, int bnq)
{
    uint32_t smb = smem_u32(gsm);
    const int tid = threadIdx.x;
    const int wid = tid >> 5, lane = tid & 31;
    const int lr = lane >> 2, lc = lane & 3;
    const int bm = bmq << 7, bn = bnq << 7;
    const int wm = (wid & 3) << 5, wn = (wid >> 2) << 6;

    // ldmatrix per-lane address offsets (half units)
    const int a_row_off = (((lane >> 3) & 1) << 3) + (lane & 7);
    const int a_col_off = ((lane >> 4) & 1) << 3;
    const int b_row_off = (((lane >> 4) & 1) << 3) + (lane & 7);
    const int b_col_off = ((lane >> 3) & 1) << 3;

    float acc[2][8][4];
#pragma unroll
    for (int im = 0; im < 2; im++)
#pragma unroll
        for (int jn = 0; jn < 8; jn++)
#pragma unroll
            for (int t = 0; t < 4; t++) acc[im][jn][t] = 0.f;

#define GLOADL(st, ch)                                                         \
    {                                                                          \
        uint32_t ab = smb + (st) * (G_STAGE_H * 2);                            \
        uint32_t bb = ab + 128 * GST * 2;                                      \
        _Pragma("unroll")                                                      \
        for (int i = 0; i < 2; i++) {                                          \
            int idx = tid + (i << 8);                                          \
            int r = idx >> 2, c = idx & 3;                                     \
            cp16(ab + r * 80 + c * 16,                                         \
                 A + (size_t)(bm + r) * HIDs + (ch) * 32 + c * 8);             \
            cp16(bb + r * 80 + c * 16,                                         \
                 Bt + (size_t)(bn + r) * HIDs + (ch) * 32 + c * 8);            \
        }                                                                      \
        asm volatile("cp.async.commit_group;");                                \
    }

    GLOADL(0, 0);
    GLOADL(1, 1);
    GLOADL(2, 2);

    for (int it = 0; it < 64; it++) {
        asm volatile("cp.async.wait_group 2;");
        __syncthreads();
        if (it + 3 < 64) {
            GLOADL((it + 3) & 3, it + 3);
        } else {
            asm volatile("cp.async.commit_group;");
        }

        uint32_t abase = smb + (it & 3) * (G_STAGE_H * 2);
        uint32_t bbase = abase + 128 * GST * 2;
#pragma unroll
        for (int kk = 0; kk < 2; kk++) {
            const int kc = kk << 4;
            uint32_t af[2][4];
#pragma unroll
            for (int im = 0; im < 2; im++)
                ldsm4(af[im], abase +
                      (uint32_t)(((wm + (im << 4) + a_row_off) * GST +
                                  kc + a_col_off) << 1));
#pragma unroll
            for (int p = 0; p < 4; p++) {
                uint32_t bf[4];
                ldsm4(bf, bbase +
                      (uint32_t)(((wn + (p << 4) + b_row_off) * GST +
                                  kc + b_col_off) << 1));
                mma16(acc[0][2 * p],     af[0], bf);
                mma16(acc[1][2 * p],     af[1], bf);
                mma16(acc[0][2 * p + 1], af[0], bf + 2);
                mma16(acc[1][2 * p + 1], af[1], bf + 2);
            }
        }
    }
#undef GLOADL

#pragma unroll
    for (int im = 0; im < 2; im++) {
        int row = bm + wm + (im << 4) + lr;
#pragma unroll
        for (int jn = 0; jn < 8; jn++) {
            int col = bn + wn + (jn << 3) + (lc << 1);
            float b0 = bias ? bias[col] : 0.f;
            float b1 = bias ? bias[col + 1] : 0.f;
            float v0 = acc[im][jn][0] + b0, v1 = acc[im][jn][1] + b1;
            float v2 = acc[im][jn][2] + b0, v3 = acc[im][jn][3] + b1;
            if (out_half) {
                __half* C = (__half*)Cout;
                *(__half2*)(C + (size_t)row * HIDs + col) = __floats2half2_rn(v0, v1);
                *(__half2*)(C + (size_t)(row + 8) * HIDs + col) = __floats2half2_rn(v2, v3);
            } else {
                float* C = (float*)Cout;
                *(float2*)(C + (size_t)row * HIDs + col) = make_float2(v0, v1);
                *(float2*)(C + (size_t)(row + 8) * HIDs + col) = make_float2(v2, v3);
            }
        }
    }
}

// fused Q/K/V projection: blockIdx.z picks weight/bias/output
__global__ __launch_bounds__(256, 2)
void qkv_gemm(const __half* __restrict__ A,
              const __half* __restrict__ w0, const __half* __restrict__ w1,
              const __half* __restrict__ w2,
              const float* __restrict__ b0, const float* __restrict__ b1,
              const float* __restrict__ b2,
              __half* __restrict__ c0, __half* __restrict__ c1,
              __half* __restrict__ c2)
{
    extern __shared__ __half gsm[];
    const __half* W = (blockIdx.z == 0) ? w0 : (blockIdx.z == 1) ? w1 : w2;
    const float* B  = (blockIdx.z == 0) ? b0 : (blockIdx.z == 1) ? b1 : b2;
    __half* C       = (blockIdx.z == 0) ? c0 : (blockIdx.z == 1) ? c1 : c2;
    gemm_body(A, W, B, C, 1, gsm, blockIdx.y, blockIdx.x);
}

__global__ __launch_bounds__(256, 2)
void out_gemm(const __half* __restrict__ A, const __half* __restrict__ Bt,
              float* __restrict__ C)
{
    extern __shared__ __half gsm[];
    gemm_body(A, Bt, nullptr, C, 0, gsm, blockIdx.y, blockIdx.x);
}

// ---------------- RoPE (q also pre-scaled by 128^-0.5) ----------------
__global__ void rope_h(__half* __restrict__ q, __half* __restrict__ k,
                       const int* __restrict__ positions)
{
    int idx = blockIdx.x * blockDim.x + threadIdx.x;
    if (idx >= Mrows * NHh * 64) return;
    int d = idx & 63;
    int t = idx >> 6;
    int h = t % NHh;
    int m = t / NHh;
    const float SC = 0.08838834764831845f;

    float pos = (float)positions[m];
    float invf = powf(10000.0f, -(float)d * (1.0f / 64.0f));
    float fr = pos * invf;
    float c = cosf(fr), s = sinf(fr);

    size_t base = (size_t)m * HIDs + h * HDd;
    float q1 = __half2float(q[base + d]), q2 = __half2float(q[base + 64 + d]);
    q[base + d]      = __float2half((q1 * c - q2 * s) * SC);
    q[base + 64 + d] = __float2half((q2 * c + q1 * s) * SC);
    float k1 = __half2float(k[base + d]), k2 = __half2float(k[base + 64 + d]);
    k[base + d]      = __float2half(k1 * c - k2 * s);
    k[base + 64 + d] = __float2half(k2 * c + k1 * s);
}

// ---------------- flash attention fp16, double-buffered K/V ----------------
#define QS_OFF 0
#define KS_OFF 17408
#define KBUF   8704
#define VT_OFF 34816
#define VBUF   9792
#define F_HALFS 54400

__global__ __launch_bounds__(256, 1)
void flash_h(const __half* __restrict__ Q, const __half* __restrict__ K,
             const __half* __restrict__ Vt, __half* __restrict__ O)
{
    extern __shared__ __half fsm[];
    __half* Qs = fsm;
    __half* Ps = fsm;
    uint32_t smb = smem_u32(fsm);

    const int tid = threadIdx.x;
    const int wid = tid >> 5, lane = tid & 31;
    const int lr = lane >> 2, lc = lane & 3;
    const int bh = blockIdx.y, b = bh >> 4, h = bh & 15;
    const int q0 = blockIdx.x << 7;
    const int wrow = wid << 4;
    const int nkt = (q0 >> 6) + 2;
    const float L2E = 1.44269504f;
    const size_t qbase = (size_t)(b * Ssz) * HIDs + (size_t)h * HDd;
    const size_t vtbase = (size_t)bh * HDd * Ssz;

    for (int i = tid; i < 2 * 8 * 72; i += 256) {
        int bufi = i / (8 * 72);
        int rem = i % (8 * 72);
        int rr = rem / 72, cc = rem % 72;
        fsm[VT_OFF + bufi * VBUF + (128 + rr) * 72 + cc] =
            (rr == 0 && cc < 64) ? __float2half(1.f) : __float2half(0.f);
    }

#pragma unroll
    for (int i = 0; i < 8; i++) {
        int idx = tid + (i << 8);
        int r = idx >> 4, c = idx & 15;
        cp16(smb + r * 272 + c * 16, Q + qbase + (size_t)(q0 + r) * HIDs + c * 8);
    }
    asm volatile("cp.async.commit_group;");
    asm volatile("cp.async.wait_group 0;");
    __syncthreads();

    uint32_t qf[8][4];
#pragma unroll
    for (int kk = 0; kk < 8; kk++) {
        int r0 = wrow + lr;
        int c0 = (kk << 4) + (lc << 1);
        qf[kk][0] = *(const uint32_t*)(Qs + r0 * 136 + c0);
        qf[kk][1] = *(const uint32_t*)(Qs + (r0 + 8) * 136 + c0);
        qf[kk][2] = *(const uint32_t*)(Qs + r0 * 136 + c0 + 8);
        qf[kk][3] = *(const uint32_t*)(Qs + (r0 + 8) * 136 + c0 + 8);
    }

#pragma unroll
    for (int i = 0; i < 4; i++) {
        int idx = tid + (i << 8);
        int r = idx >> 4, c = idx & 15;
        cp16(smb + KS_OFF * 2 + r * 272 + c * 16,
             K + qbase + (size_t)r * HIDs + c * 8);
        int r2 = idx >> 3, c2 = idx & 7;
        cp16(smb + VT_OFF * 2 + r2 * 144 + c2 * 16,
             Vt + vtbase + (size_t)r2 * Ssz + c2 * 8);
    }
    asm volatile("cp.async.commit_group;");

    float oacc[17][4];
#pragma unroll
    for (int nt = 0; nt < 17; nt++)
#pragma unroll
        for (int t = 0; t < 4; t++) oacc[nt][t] = 0.f;
    float m0 = -1e30f, m1 = -1e30f;

    for (int kt = 0; kt < nkt; kt++) {
        const int buf = kt & 1;
        __syncthreads();
        if (kt + 1 < nkt) {
            const int nb = buf ^ 1;
            const int k0n = (kt + 1) << 6;
#pragma unroll
            for (int i = 0; i < 4; i++) {
                int idx = tid + (i << 8);
                int r = idx >> 4, c = idx & 15;
                cp16(smb + (KS_OFF + nb * KBUF) * 2 + r * 272 + c * 16,
                     K + qbase + (size_t)(k0n + r) * HIDs + c * 8);
                int r2 = idx >> 3, c2 = idx & 7;
                cp16(smb + (VT_OFF + nb * VBUF) * 2 + r2 * 144 + c2 * 16,
                     Vt + vtbase + (size_t)r2 * Ssz + k0n + c2 * 8);
            }
        }
        asm volatile("cp.async.commit_group;");
        if (kt + 1 < nkt) asm volatile("cp.async.wait_group 1;");
        else              asm volatile("cp.async.wait_group 0;");
        __syncthreads();

        const __half* Ks = fsm + KS_OFF + buf * KBUF;
        const __half* Vs = fsm + VT_OFF + buf * VBUF;
        const int k0 = kt << 6;

        float sacc[8][4];
#pragma unroll
        for (int jn = 0; jn < 8; jn++)
#pragma unroll
            for (int t = 0; t < 4; t++) sacc[jn][t] = 0.f;
#pragma unroll
        for (int kk = 0; kk < 8; kk++) {
            const int kc = (kk << 4) + (lc << 1);
#pragma unroll
            for (int jn = 0; jn < 8; jn++) {
                int n = (jn << 3) + lr;
                uint32_t bf[2];
                bf[0] = *(const uint32_t*)(Ks + n * 136 + kc);
                bf[1] = *(const uint32_t*)(Ks + n * 136 + kc + 8);
                mma16(sacc[jn], qf[kk], bf);
            }
        }

        const int rg0 = q0 + wrow + lr;
        if (k0 + 63 > q0 + wrow) {
#pragma unroll
            for (int jn = 0; jn < 8; jn++) {
                int cg = k0 + (jn << 3) + (lc << 1);
                if (cg > rg0)         sacc[jn][0] = -1e30f;
                if (cg + 1 > rg0)     sacc[jn][1] = -1e30f;
                if (cg > rg0 + 8)     sacc[jn][2] = -1e30f;
                if (cg + 1 > rg0 + 8) sacc[jn][3] = -1e30f;
            }
        }

        float mx0 = -1e30f, mx1 = -1e30f;
#pragma unroll
        for (int jn = 0; jn < 8; jn++) {
            mx0 = fmaxf(mx0, fmaxf(sacc[jn][0], sacc[jn][1]));
            mx1 = fmaxf(mx1, fmaxf(sacc[jn][2], sacc[jn][3]));
        }
        mx0 = fmaxf(mx0, __shfl_xor_sync(0xffffffffu, mx0, 1));
        mx0 = fmaxf(mx0, __shfl_xor_sync(0xffffffffu, mx0, 2));
        mx1 = fmaxf(mx1, __shfl_xor_sync(0xffffffffu, mx1, 1));
        mx1 = fmaxf(mx1, __shfl_xor_sync(0xffffffffu, mx1, 2));

        if (mx0 > m0 || mx1 > m1) {
            float mn0 = fmaxf(m0, mx0), mn1 = fmaxf(m1, mx1);
            float cf0 = exp2f((m0 - mn0) * L2E);
            float cf1 = exp2f((m1 - mn1) * L2E);
#pragma unroll
            for (int nt = 0; nt < 17; nt++) {
                oacc[nt][0] *= cf0; oacc[nt][1] *= cf0;
                oacc[nt][2] *= cf1; oacc[nt][3] *= cf1;
            }
            m0 = mn0; m1 = mn1;
        }

        const float mls0 = m0 * L2E, mls1 = m1 * L2E;
        const int pr = wrow + lr;
#pragma unroll
        for (int jn = 0; jn < 8; jn++) {
            int pc = (jn << 3) + (lc << 1);
            uint32_t p01 = ex2h2(fmaf(sacc[jn][0], L2E, -mls0),
                                 fmaf(sacc[jn][1], L2E, -mls0));
            uint32_t p23 = ex2h2(fmaf(sacc[jn][2], L2E, -mls1),
                                 fmaf(sacc[jn][3], L2E, -mls1));
            *(uint32_t*)(Ps + pr * 72 + pc) = p01;
            *(uint32_t*)(Ps + (pr + 8) * 72 + pc) = p23;
        }
        __syncwarp();

#pragma unroll
        for (int kk = 0; kk < 4; kk++) {
            const int kc = (kk << 4) + (lc << 1);
            uint32_t af[4];
            af[0] = *(const uint32_t*)(Ps + pr * 72 + kc);
            af[1] = *(const uint32_t*)(Ps + (pr + 8) * 72 + kc);
            af[2] = *(const uint32_t*)(Ps + pr * 72 + kc + 8);
            af[3] = *(const uint32_t*)(Ps + (pr + 8) * 72 + kc + 8);
#pragma unroll
            for (int nt = 0; nt < 17; nt++) {
                int n = (nt << 3) + lr;
                uint32_t bf[2];
                bf[0] = *(const uint32_t*)(Vs + n * 72 + kc);
                bf[1] = *(const uint32_t*)(Vs + n * 72 + kc + 8);
                mma16(oacc[nt], af, bf);
            }
        }
    }

    float l0 = __shfl_sync(0xffffffffu, oacc[16][0], lane & 28);
    float l1 = __shfl_sync(0xffffffffu, oacc[16][2], lane & 28);
    float i0 = 1.f / l0, i1 = 1.f / l1;
    const int row = q0 + wrow + lr;
#pragma unroll
    for (int nt = 0; nt < 16; nt++) {
        int col = (nt << 3) + (lc << 1);
        *(__half2*)(O + qbase + (size_t)row * HIDs + col) =
            __floats2half2_rn(oacc[nt][0] * i0, oacc[nt][1] * i0);
        *(__half2*)(O + qbase + (size_t)(row + 8) * HIDs + col) =
            __floats2half2_rn(oacc[nt][2] * i1, oacc[nt][3] * i1);
    }
}

// ---------------------------------------------------------------------------
extern "C" void kernel_launch(void* const* d_in, const int* in_sizes, int n_in,
                              void* d_out, int out_size)
{
    (void)in_sizes; (void)n_in; (void)out_size;
    const float* hidden    = (const float*)d_in[0];
    const int*   positions = (const int*)  d_in[1];
    const float* wq = (const float*)d_in[2];
    const float* bq = (const float*)d_in[3];
    const float* wk = (const float*)d_in[4];
    const float* bk = (const float*)d_in[5];
    const float* wv = (const float*)d_in[6];
    const float* bv = (const float*)d_in[7];
    const float* wc = (const float*)d_in[8];
    float* out = (float*)d_out;

    __half *hp, *qp, *kp, *vp, *vtp, *ap, *wqp, *wkp, *wvp, *wcp;
    cudaGetSymbolAddress((void**)&hp,  g_hid);
    cudaGetSymbolAddress((void**)&qp,  g_q);
    cudaGetSymbolAddress((void**)&kp,  g_k);
    cudaGetSymbolAddress((void**)&vp,  g_v);
    cudaGetSymbolAddress((void**)&vtp, g_vt);
    cudaGetSymbolAddress((void**)&ap,  g_attn);
    cudaGetSymbolAddress((void**)&wqp, g_wq);
    cudaGetSymbolAddress((void**)&wkp, g_wk);
    cudaGetSymbolAddress((void**)&wvp, g_wv);
    cudaGetSymbolAddress((void**)&wcp, g_wc);

    cvth<<<(Mrows*HIDs/4 + 255)/256, 256>>>(hidden, hp, Mrows*HIDs/4);
    wtrh4<<<dim3(HIDs/32, HIDs/32, 4), dim3(32, 8)>>>(wq, wk, wv, wc,
                                                      wqp, wkp, wvp, wcp);

    cudaFuncSetAttribute(qkv_gemm, cudaFuncAttributeMaxDynamicSharedMemorySize, G_SMEM);
    cudaFuncSetAttribute(out_gemm, cudaFuncAttributeMaxDynamicSharedMemorySize, G_SMEM);

    qkv_gemm<<<dim3(HIDs/128, Mrows/128, 3), 256, G_SMEM>>>(
        hp, wqp, wkp, wvp, bq, bk, bv, qp, kp, vp);

    rope_h<<<(Mrows * NHh * 64) / 256, 256>>>(qp, kp, positions);
    vtrans<<<dim3(Ssz/32, HDd/32, Bsz*NHh), dim3(32, 8)>>>(vp, vtp);

    cudaFuncSetAttribute(flash_h, cudaFuncAttributeMaxDynamicSharedMemorySize,
                         F_HALFS * 2);
    flash_h<<<dim3(Ssz / 128, Bsz * NHh), 256, F_HALFS * 2>>>(qp, kp, vtp, ap);

    out_gemm<<<dim3(HIDs/128, Mrows/128), 256, G_SMEM>>>(ap, wcp, out);
}

// round 15
// speedup vs baseline: 1.3185x; 1.3185x over previous
#include <cuda_runtime.h>
#include <cuda_fp16.h>
#include <math.h>
#include <stdint.h>

#define Bsz  2
#define Ssz  2048
#define HIDs 2048
#define NHh  16
#define HDd  128
#define Mrows (Bsz*Ssz)

__device__ __half g_hid[Mrows*HIDs];
__device__ __half g_q[Mrows*HIDs];
__device__ __half g_k[Mrows*HIDs];
__device__ __half g_v[Mrows*HIDs];
__device__ __half g_vt[Mrows*HIDs];     // [bh][d][s]
__device__ __half g_attn[Mrows*HIDs];
__device__ __half g_wq[HIDs*HIDs];      // [N][K]
__device__ __half g_wk[HIDs*HIDs];
__device__ __half g_wv[HIDs*HIDs];
__device__ __half g_wc[HIDs*HIDs];

__device__ __forceinline__ void mma16(float* c, const uint32_t* a, const uint32_t* b) {
    asm volatile(
        "mma.sync.aligned.m16n8k16.row.col.f32.f16.f16.f32 "
        "{%0,%1,%2,%3}, {%4,%5,%6,%7}, {%8,%9}, {%0,%1,%2,%3};"
        : "+f"(c[0]), "+f"(c[1]), "+f"(c[2]), "+f"(c[3])
        : "r"(a[0]), "r"(a[1]), "r"(a[2]), "r"(a[3]), "r"(b[0]), "r"(b[1]));
}
__device__ __forceinline__ void cp16(uint32_t saddr, const void* g) {
    asm volatile("cp.async.cg.shared.global [%0], [%1], 16;" :: "r"(saddr), "l"(g));
}
__device__ __forceinline__ uint32_t smem_u32(const void* p) {
    return (uint32_t)__cvta_generic_to_shared(p);
}
__device__ __forceinline__ uint32_t ex2h2(float x0, float x1) {
    __half2 h = __floats2half2_rn(x0, x1);
    uint32_t u = *reinterpret_cast<uint32_t*>(&h);
    uint32_t r;
    asm volatile("ex2.approx.f16x2 %0, %1;" : "=r"(r) : "r"(u));
    return r;
}

// ---------------- prep ----------------
__global__ void cvth(const float* __restrict__ in, __half* __restrict__ out, int n4) {
    int i = blockIdx.x * blockDim.x + threadIdx.x;
    if (i < n4) {
        float4 v = ((const float4*)in)[i];
        __half2 h0 = __floats2half2_rn(v.x, v.y);
        __half2 h1 = __floats2half2_rn(v.z, v.w);
        uint2 u;
        u.x = *reinterpret_cast<uint32_t*>(&h0);
        u.y = *reinterpret_cast<uint32_t*>(&h1);
        ((uint2*)out)[i] = u;
    }
}

// 4 weights transposed in one launch (z picks the matrix)
__global__ void wtrh4(const float* __restrict__ i0, const float* __restrict__ i1,
                      const float* __restrict__ i2, const float* __restrict__ i3,
                      __half* __restrict__ o0, __half* __restrict__ o1,
                      __half* __restrict__ o2, __half* __restrict__ o3) {
    const float* in  = (blockIdx.z == 0) ? i0 : (blockIdx.z == 1) ? i1
                     : (blockIdx.z == 2) ? i2 : i3;
    __half* out      = (blockIdx.z == 0) ? o0 : (blockIdx.z == 1) ? o1
                     : (blockIdx.z == 2) ? o2 : o3;
    __shared__ float t[32][33];
    int bx = blockIdx.x << 5, by = blockIdx.y << 5;
#pragma unroll
    for (int i = 0; i < 4; i++) {
        int k = by + threadIdx.y + (i << 3);
        t[threadIdx.y + (i << 3)][threadIdx.x] = in[(size_t)k * HIDs + bx + threadIdx.x];
    }
    __syncthreads();
#pragma unroll
    for (int i = 0; i < 4; i++) {
        int n = bx + threadIdx.y + (i << 3);
        out[(size_t)n * HIDs + by + threadIdx.x] =
            __float2half(t[threadIdx.x][threadIdx.y + (i << 3)]);
    }
}

// v[b][s][h*128+d] -> vt[bh][d][s]
__global__ void vtrans(const __half* __restrict__ v, __half* __restrict__ vt) {
    __shared__ __half t[32][33];
    int bh = blockIdx.z;
    int b = bh >> 4, h = bh & 15;
    int s0 = blockIdx.x << 5, d0 = blockIdx.y << 5;
#pragma unroll
    for (int i = 0; i < 4; i++) {
        int s = s0 + threadIdx.y + (i << 3);
        t[threadIdx.y + (i << 3)][threadIdx.x] =
            v[((size_t)(b * Ssz + s)) * HIDs + h * HDd + d0 + threadIdx.x];
    }
    __syncthreads();
#pragma unroll
    for (int i = 0; i < 4; i++) {
        int d = d0 + threadIdx.y + (i << 3);
        vt[((size_t)bh * HDd + d) * Ssz + s0 + threadIdx.x] =
            t[threadIdx.x][threadIdx.y + (i << 3)];
    }
}

// ---------------- fp16 GEMM (R6, measured ~105us/GEMM): C = A @ Bt^T --------
#define GST 40
#define G_STAGE_H (2*128*GST)
#define G_SMEM (4*G_STAGE_H*2)

__global__ __launch_bounds__(256, 2)
void tgemm_h(const __half* __restrict__ A, const __half* __restrict__ Bt,
             const float* __restrict__ bias, void* __restrict__ Cout, int out_half)
{
    extern __shared__ __half gsm[];
    uint32_t smb = smem_u32(gsm);
    const int tid = threadIdx.x;
    const int wid = tid >> 5, lane = tid & 31;
    const int lr = lane >> 2, lc = lane & 3;
    const int bm = blockIdx.y << 7, bn = blockIdx.x << 7;
    const int wm = (wid & 3) << 5, wn = (wid >> 2) << 6;

    float acc[2][8][4];
#pragma unroll
    for (int im = 0; im < 2; im++)
#pragma unroll
        for (int jn = 0; jn < 8; jn++)
#pragma unroll
            for (int t = 0; t < 4; t++) acc[im][jn][t] = 0.f;

#define GLOAD(st, ch)                                                          \
    {                                                                          \
        uint32_t ab = smb + (st) * (G_STAGE_H * 2);                            \
        uint32_t bb = ab + 128 * GST * 2;                                      \
        _Pragma("unroll")                                                      \
        for (int i = 0; i < 2; i++) {                                          \
            int idx = tid + (i << 8);                                          \
            int r = idx >> 2, c = idx & 3;                                     \
            cp16(ab + r * 80 + c * 16,                                         \
                 A + (size_t)(bm + r) * HIDs + (ch) * 32 + c * 8);             \
            cp16(bb + r * 80 + c * 16,                                         \
                 Bt + (size_t)(bn + r) * HIDs + (ch) * 32 + c * 8);            \
        }                                                                      \
        asm volatile("cp.async.commit_group;");                                \
    }

    GLOAD(0, 0);
    GLOAD(1, 1);
    GLOAD(2, 2);

    for (int it = 0; it < 64; it++) {
        asm volatile("cp.async.wait_group 2;");
        __syncthreads();
        if (it + 3 < 64) {
            GLOAD((it + 3) & 3, it + 3);
        } else {
            asm volatile("cp.async.commit_group;");
        }

        const __half* as = gsm + (it & 3) * G_STAGE_H;
        const __half* bs = as + 128 * GST;
#pragma unroll
        for (int kk = 0; kk < 2; kk++) {
            const int kc = (kk << 4) + (lc << 1);
            uint32_t af[2][4];
#pragma unroll
            for (int im = 0; im < 2; im++) {
                int m = wm + (im << 4) + lr;
                af[im][0] = *(const uint32_t*)(as + m * GST + kc);
                af[im][1] = *(const uint32_t*)(as + (m + 8) * GST + kc);
                af[im][2] = *(const uint32_t*)(as + m * GST + kc + 8);
                af[im][3] = *(const uint32_t*)(as + (m + 8) * GST + kc + 8);
            }
#pragma unroll
            for (int jn = 0; jn < 8; jn++) {
                int n = wn + (jn << 3) + lr;
                uint32_t bf[2];
                bf[0] = *(const uint32_t*)(bs + n * GST + kc);
                bf[1] = *(const uint32_t*)(bs + n * GST + kc + 8);
                mma16(acc[0][jn], af[0], bf);
                mma16(acc[1][jn], af[1], bf);
            }
        }
    }
#undef GLOAD

#pragma unroll
    for (int im = 0; im < 2; im++) {
        int row = bm + wm + (im << 4) + lr;
#pragma unroll
        for (int jn = 0; jn < 8; jn++) {
            int col = bn + wn + (jn << 3) + (lc << 1);
            float b0 = bias ? bias[col] : 0.f;
            float b1 = bias ? bias[col + 1] : 0.f;
            float v0 = acc[im][jn][0] + b0, v1 = acc[im][jn][1] + b1;
            float v2 = acc[im][jn][2] + b0, v3 = acc[im][jn][3] + b1;
            if (out_half) {
                __half* C = (__half*)Cout;
                *(__half2*)(C + (size_t)row * HIDs + col) = __floats2half2_rn(v0, v1);
                *(__half2*)(C + (size_t)(row + 8) * HIDs + col) = __floats2half2_rn(v2, v3);
            } else {
                float* C = (float*)Cout;
                *(float2*)(C + (size_t)row * HIDs + col) = make_float2(v0, v1);
                *(float2*)(C + (size_t)(row + 8) * HIDs + col) = make_float2(v2, v3);
            }
        }
    }
}

// ---------------- RoPE (q also pre-scaled by 128^-0.5) ----------------
__global__ void rope_h(__half* __restrict__ q, __half* __restrict__ k,
                       const int* __restrict__ positions)
{
    int idx = blockIdx.x * blockDim.x + threadIdx.x;
    if (idx >= Mrows * NHh * 64) return;
    int d = idx & 63;
    int t = idx >> 6;
    int h = t % NHh;
    int m = t / NHh;
    const float SC = 0.08838834764831845f;

    float pos = (float)positions[m];
    float invf = powf(10000.0f, -(float)d * (1.0f / 64.0f));
    float fr = pos * invf;
    float c = cosf(fr), s = sinf(fr);

    size_t base = (size_t)m * HIDs + h * HDd;
    float q1 = __half2float(q[base + d]), q2 = __half2float(q[base + 64 + d]);
    q[base + d]      = __float2half((q1 * c - q2 * s) * SC);
    q[base + 64 + d] = __float2half((q2 * c + q1 * s) * SC);
    float k1 = __half2float(k[base + d]), k2 = __half2float(k[base + 64 + d]);
    k[base + d]      = __float2half(k1 * c - k2 * s);
    k[base + 64 + d] = __float2half(k2 * c + k1 * s);
}

// ---------------- flash attention fp16, double-buffered K/V (R9) ------------
#define QS_OFF 0
#define KS_OFF 17408
#define KBUF   8704
#define VT_OFF 34816
#define VBUF   9792
#define F_HALFS 54400

__global__ __launch_bounds__(256, 1)
void flash_h(const __half* __restrict__ Q, const __half* __restrict__ K,
             const __half* __restrict__ Vt, __half* __restrict__ O)
{
    extern __shared__ __half fsm[];
    __half* Qs = fsm;
    __half* Ps = fsm;
    uint32_t smb = smem_u32(fsm);

    const int tid = threadIdx.x;
    const int wid = tid >> 5, lane = tid & 31;
    const int lr = lane >> 2, lc = lane & 3;
    const int bh = blockIdx.y, b = bh >> 4, h = bh & 15;
    const int q0 = blockIdx.x << 7;
    const int wrow = wid << 4;
    const int nkt = (q0 >> 6) + 2;
    const float L2E = 1.44269504f;
    const size_t qbase = (size_t)(b * Ssz) * HIDs + (size_t)h * HDd;
    const size_t vtbase = (size_t)bh * HDd * Ssz;

    for (int i = tid; i < 2 * 8 * 72; i += 256) {
        int bufi = i / (8 * 72);
        int rem = i % (8 * 72);
        int rr = rem / 72, cc = rem % 72;
        fsm[VT_OFF + bufi * VBUF + (128 + rr) * 72 + cc] =
            (rr == 0 && cc < 64) ? __float2half(1.f) : __float2half(0.f);
    }

#pragma unroll
    for (int i = 0; i < 8; i++) {
        int idx = tid + (i << 8);
        int r = idx >> 4, c = idx & 15;
        cp16(smb + r * 272 + c * 16, Q + qbase + (size_t)(q0 + r) * HIDs + c * 8);
    }
    asm volatile("cp.async.commit_group;");
    asm volatile("cp.async.wait_group 0;");
    __syncthreads();

    uint32_t qf[8][4];
#pragma unroll
    for (int kk = 0; kk < 8; kk++) {
        int r0 = wrow + lr;
        int c0 = (kk << 4) + (lc << 1);
        qf[kk][0] = *(const uint32_t*)(Qs + r0 * 136 + c0);
        qf[kk][1] = *(const uint32_t*)(Qs + (r0 + 8) * 136 + c0);
        qf[kk][2] = *(const uint32_t*)(Qs + r0 * 136 + c0 + 8);
        qf[kk][3] = *(const uint32_t*)(Qs + (r0 + 8) * 136 + c0 + 8);
    }

#pragma unroll
    for (int i = 0; i < 4; i++) {
        int idx = tid + (i << 8);
        int r = idx >> 4, c = idx & 15;
        cp16(smb + KS_OFF * 2 + r * 272 + c * 16,
             K + qbase + (size_t)r * HIDs + c * 8);
        int r2 = idx >> 3, c2 = idx & 7;
        cp16(smb + VT_OFF * 2 + r2 * 144 + c2 * 16,
             Vt + vtbase + (size_t)r2 * Ssz + c2 * 8);
    }
    asm volatile("cp.async.commit_group;");

    float oacc[17][4];
#pragma unroll
    for (int nt = 0; nt < 17; nt++)
#pragma unroll
        for (int t = 0; t < 4; t++) oacc[nt][t] = 0.f;
    float m0 = -1e30f, m1 = -1e30f;

    for (int kt = 0; kt < nkt; kt++) {
        const int buf = kt & 1;
        __syncthreads();
        if (kt + 1 < nkt) {
            const int nb = buf ^ 1;
            const int k0n = (kt + 1) << 6;
#pragma unroll
            for (int i = 0; i < 4; i++) {
                int idx = tid + (i << 8);
                int r = idx >> 4, c = idx & 15;
                cp16(smb + (KS_OFF + nb * KBUF) * 2 + r * 272 + c * 16,
                     K + qbase + (size_t)(k0n + r) * HIDs + c * 8);
                int r2 = idx >> 3, c2 = idx & 7;
                cp16(smb + (VT_OFF + nb * VBUF) * 2 + r2 * 144 + c2 * 16,
                     Vt + vtbase + (size_t)r2 * Ssz + k0n + c2 * 8);
            }
        }
        asm volatile("cp.async.commit_group;");
        if (kt + 1 < nkt) asm volatile("cp.async.wait_group 1;");
        else              asm volatile("cp.async.wait_group 0;");
        __syncthreads();

        const __half* Ks = fsm + KS_OFF + buf * KBUF;
        const __half* Vs = fsm + VT_OFF + buf * VBUF;
        const int k0 = kt << 6;

        float sacc[8][4];
#pragma unroll
        for (int jn = 0; jn < 8; jn++)
#pragma unroll
            for (int t = 0; t < 4; t++) sacc[jn][t] = 0.f;
#pragma unroll
        for (int kk = 0; kk < 8; kk++) {
            const int kc = (kk << 4) + (lc << 1);
#pragma unroll
            for (int jn = 0; jn < 8; jn++) {
                int n = (jn << 3) + lr;
                uint32_t bf[2];
                bf[0] = *(const uint32_t*)(Ks + n * 136 + kc);
                bf[1] = *(const uint32_t*)(Ks + n * 136 + kc + 8);
                mma16(sacc[jn], qf[kk], bf);
            }
        }

        const int rg0 = q0 + wrow + lr;
        if (k0 + 63 > q0 + wrow) {
#pragma unroll
            for (int jn = 0; jn < 8; jn++) {
                int cg = k0 + (jn << 3) + (lc << 1);
                if (cg > rg0)         sacc[jn][0] = -1e30f;
                if (cg + 1 > rg0)     sacc[jn][1] = -1e30f;
                if (cg > rg0 + 8)     sacc[jn][2] = -1e30f;
                if (cg + 1 > rg0 + 8) sacc[jn][3] = -1e30f;
            }
        }

        float mx0 = -1e30f, mx1 = -1e30f;
#pragma unroll
        for (int jn = 0; jn < 8; jn++) {
            mx0 = fmaxf(mx0, fmaxf(sacc[jn][0], sacc[jn][1]));
            mx1 = fmaxf(mx1, fmaxf(sacc[jn][2], sacc[jn][3]));
        }
        mx0 = fmaxf(mx0, __shfl_xor_sync(0xffffffffu, mx0, 1));
        mx0 = fmaxf(mx0, __shfl_xor_sync(0xffffffffu, mx0, 2));
        mx1 = fmaxf(mx1, __shfl_xor_sync(0xffffffffu, mx1, 1));
        mx1 = fmaxf(mx1, __shfl_xor_sync(0xffffffffu, mx1, 2));

        if (mx0 > m0 || mx1 > m1) {
            float mn0 = fmaxf(m0, mx0), mn1 = fmaxf(m1, mx1);
            float cf0 = exp2f((m0 - mn0) * L2E);
            float cf1 = exp2f((m1 - mn1) * L2E);
#pragma unroll
            for (int nt = 0; nt < 17; nt++) {
                oacc[nt][0] *= cf0; oacc[nt][1] *= cf0;
                oacc[nt][2] *= cf1; oacc[nt][3] *= cf1;
            }
            m0 = mn0; m1 = mn1;
        }

        const float mls0 = m0 * L2E, mls1 = m1 * L2E;
        const int pr = wrow + lr;
#pragma unroll
        for (int jn = 0; jn < 8; jn++) {
            int pc = (jn << 3) + (lc << 1);
            uint32_t p01 = ex2h2(fmaf(sacc[jn][0], L2E, -mls0),
                                 fmaf(sacc[jn][1], L2E, -mls0));
            uint32_t p23 = ex2h2(fmaf(sacc[jn][2], L2E, -mls1),
                                 fmaf(sacc[jn][3], L2E, -mls1));
            *(uint32_t*)(Ps + pr * 72 + pc) = p01;
            *(uint32_t*)(Ps + (pr + 8) * 72 + pc) = p23;
        }
        __syncwarp();

#pragma unroll
        for (int kk = 0; kk < 4; kk++) {
            const int kc = (kk << 4) + (lc << 1);
            uint32_t af[4];
            af[0] = *(const uint32_t*)(Ps + pr * 72 + kc);
            af[1] = *(const uint32_t*)(Ps + (pr + 8) * 72 + kc);
            af[2] = *(const uint32_t*)(Ps + pr * 72 + kc + 8);
            af[3] = *(const uint32_t*)(Ps + (pr + 8) * 72 + kc + 8);
#pragma unroll
            for (int nt = 0; nt < 17; nt++) {
                int n = (nt << 3) + lr;
                uint32_t bf[2];
                bf[0] = *(const uint32_t*)(Vs + n * 72 + kc);
                bf[1] = *(const uint32_t*)(Vs + n * 72 + kc + 8);
                mma16(oacc[nt], af, bf);
            }
        }
    }

    float l0 = __shfl_sync(0xffffffffu, oacc[16][0], lane & 28);
    float l1 = __shfl_sync(0xffffffffu, oacc[16][2], lane & 28);
    float i0 = 1.f / l0, i1 = 1.f / l1;
    const int row = q0 + wrow + lr;
#pragma unroll
    for (int nt = 0; nt < 16; nt++) {
        int col = (nt << 3) + (lc << 1);
        *(__half2*)(O + qbase + (size_t)row * HIDs + col) =
            __floats2half2_rn(oacc[nt][0] * i0, oacc[nt][1] * i0);
        *(__half2*)(O + qbase + (size_t)(row + 8) * HIDs + col) =
            __floats2half2_rn(oacc[nt][2] * i1, oacc[nt][3] * i1);
    }
}

// ---------------------------------------------------------------------------
extern "C" void kernel_launch(void* const* d_in, const int* in_sizes, int n_in,
                              void* d_out, int out_size)
{
    (void)in_sizes; (void)n_in; (void)out_size;
    const float* hidden    = (const float*)d_in[0];
    const int*   positions = (const int*)  d_in[1];
    const float* wq = (const float*)d_in[2];
    const float* bq = (const float*)d_in[3];
    const float* wk = (const float*)d_in[4];
    const float* bk = (const float*)d_in[5];
    const float* wv = (const float*)d_in[6];
    const float* bv = (const float*)d_in[7];
    const float* wc = (const float*)d_in[8];
    float* out = (float*)d_out;

    __half *hp, *qp, *kp, *vp, *vtp, *ap, *wqp, *wkp, *wvp, *wcp;
    cudaGetSymbolAddress((void**)&hp,  g_hid);
    cudaGetSymbolAddress((void**)&qp,  g_q);
    cudaGetSymbolAddress((void**)&kp,  g_k);
    cudaGetSymbolAddress((void**)&vp,  g_v);
    cudaGetSymbolAddress((void**)&vtp, g_vt);
    cudaGetSymbolAddress((void**)&ap,  g_attn);
    cudaGetSymbolAddress((void**)&wqp, g_wq);
    cudaGetSymbolAddress((void**)&wkp, g_wk);
    cudaGetSymbolAddress((void**)&wvp, g_wv);
    cudaGetSymbolAddress((void**)&wcp, g_wc);

    cvth<<<(Mrows*HIDs/4 + 255)/256, 256>>>(hidden, hp, Mrows*HIDs/4);
    wtrh4<<<dim3(HIDs/32, HIDs/32, 4), dim3(32, 8)>>>(wq, wk, wv, wc,
                                                      wqp, wkp, wvp, wcp);

    cudaFuncSetAttribute(tgemm_h, cudaFuncAttributeMaxDynamicSharedMemorySize, G_SMEM);
    dim3 gg(HIDs / 128, Mrows / 128);   // (16, 32)
    tgemm_h<<<gg, 256, G_SMEM>>>(hp, wqp, bq, qp, 1);
    tgemm_h<<<gg, 256, G_SMEM>>>(hp, wkp, bk, kp, 1);
    tgemm_h<<<gg, 256, G_SMEM>>>(hp, wvp, bv, vp, 1);

    rope_h<<<(Mrows * NHh * 64) / 256, 256>>>(qp, kp, positions);
    vtrans<<<dim3(Ssz/32, HDd/32, Bsz*NHh), dim3(32, 8)>>>(vp, vtp);

    cudaFuncSetAttribute(flash_h, cudaFuncAttributeMaxDynamicSharedMemorySize,
                         F_HALFS * 2);
    flash_h<<<dim3(Ssz / 128, Bsz * NHh), 256, F_HALFS * 2>>>(qp, kp, vtp, ap);

    tgemm_h<<<gg, 256, G_SMEM>>>(ap, wcp, nullptr, out, 0);
}